// round 13
// baseline (speedup 1.0000x reference)
#include <cuda_runtime.h>
#include <math.h>
#include <stdint.h>

// Problem constants
#define BATCH 8
#define CCH   512
#define NTOK  1024

// Scratch buffers (device globals — no allocation allowed)
__device__ float g_hn[BATCH * CCH * NTOK];        // GroupNorm1 output
__device__ float g_qkv[BATCH * 3 * CCH * NTOK];   // qkv conv output
__device__ float g_attn[BATCH * CCH * NTOK];      // attention output
__device__ float g_proj[BATCH * CCH * NTOK];      // proj conv output

// ---------------------------------------------------------------------------
// GroupNorm, vectorized: 1024 threads/block, one block per (b,g).
// ---------------------------------------------------------------------------
template <bool ADD_RES>
__global__ __launch_bounds__(1024)
void gn_kernel(const float4* __restrict__ x,
               const float* __restrict__ scale,
               const float* __restrict__ bias,
               const float4* __restrict__ resid,
               float4* __restrict__ out) {
    __shared__ float s_sum[32];
    __shared__ float s_sq[32];
    int blk = blockIdx.x;           // b*32 + g
    int g = blk & 31;
    size_t base = (size_t)blk * 4096;   // float4 units
    int tid = threadIdx.x;
    int lane = tid & 31, warp = tid >> 5;

    float sum = 0.f, sq = 0.f;
    float4 v[4];
#pragma unroll
    for (int it = 0; it < 4; it++) {
        v[it] = x[base + tid + it * 1024];
        sum += v[it].x + v[it].y + v[it].z + v[it].w;
        sq += v[it].x * v[it].x + v[it].y * v[it].y
            + v[it].z * v[it].z + v[it].w * v[it].w;
    }
#pragma unroll
    for (int o = 16; o; o >>= 1) {
        sum += __shfl_xor_sync(0xffffffffu, sum, o);
        sq  += __shfl_xor_sync(0xffffffffu, sq, o);
    }
    if (lane == 0) { s_sum[warp] = sum; s_sq[warp] = sq; }
    __syncthreads();
    if (warp == 0) {
        float a = s_sum[lane], b2 = s_sq[lane];
#pragma unroll
        for (int o = 16; o; o >>= 1) {
            a  += __shfl_xor_sync(0xffffffffu, a, o);
            b2 += __shfl_xor_sync(0xffffffffu, b2, o);
        }
        if (lane == 0) { s_sum[0] = a; s_sq[0] = b2; }
    }
    __syncthreads();
    float mean = s_sum[0] * (1.0f / 16384.0f);
    float var = s_sq[0] * (1.0f / 16384.0f) - mean * mean;
    float rstd = rsqrtf(var + 1e-5f);

#pragma unroll
    for (int it = 0; it < 4; it++) {
        int j = tid + it * 1024;            // float4 index within block slab
        int c = g * 16 + (j >> 8);          // channel (256 float4 per channel)
        float a = rstd * scale[c];
        float bb = bias[c] - mean * a;
        float4 o;
        o.x = v[it].x * a + bb;
        o.y = v[it].y * a + bb;
        o.z = v[it].z * a + bb;
        o.w = v[it].w * a + bb;
        if (ADD_RES) {
            float4 r = resid[base + j];
            o.x += r.x; o.y += r.y; o.z += r.z; o.w += r.w;
        }
        out[base + j] = o;
    }
}

// ---------------------------------------------------------------------------
// tf32 helpers
// ---------------------------------------------------------------------------
__device__ __forceinline__ float to_tf32(float x) {
    float y;
    asm("cvt.rna.tf32.f32 %0, %1;" : "=f"(y) : "f"(x));
    return y;
}

__device__ __forceinline__ void mma_tf32(float* c, const uint32_t* a, const uint32_t* b) {
    asm volatile(
        "mma.sync.aligned.m16n8k8.row.col.f32.tf32.tf32.f32 "
        "{%0,%1,%2,%3}, {%4,%5,%6,%7}, {%8,%9}, {%0,%1,%2,%3};"
        : "+f"(c[0]), "+f"(c[1]), "+f"(c[2]), "+f"(c[3])
        : "r"(a[0]), "r"(a[1]), "r"(a[2]), "r"(a[3]), "r"(b[0]), "r"(b[1]));
}

// ---------------------------------------------------------------------------
// Batched tf32 tensor-core GEMM + bias, 64x128 block tile, 128 threads
// (4 warps, 2m x 2n, warp tile 32x64), BK=32. Targets 4 blocks/SM for
// latency hiding via inter-block parallelism.
//   C[z][m][n] = sum_k A[m][k] * B[z][k][n] + bias[m]
// ---------------------------------------------------------------------------
__global__ __launch_bounds__(128)
void gemm_tf32_kernel(const float* __restrict__ A,
                      const float* __restrict__ Bm,
                      const float* __restrict__ bias,
                      float* __restrict__ Cm,
                      int M, int N, int K) {
    __shared__ float As[64][36];    // [m][k]  9216 B
    __shared__ float Bs[32][136];   // [k][n] 17408 B

    const float* B = Bm + (size_t)blockIdx.z * K * N;
    float* Cp = Cm + (size_t)blockIdx.z * M * N;
    int m0 = blockIdx.y * 64;
    int n0 = blockIdx.x * 128;
    int tid = threadIdx.x;
    int lane = tid & 31;
    int warp = tid >> 5;
    int mw = (warp >> 1) * 32;
    int nw = (warp & 1) * 64;
    int lq = lane >> 2;
    int lr = lane & 3;

    float acc[2][8][4] = {};

    for (int k0 = 0; k0 < K; k0 += 32) {
        // A tile 64x32: 512 float4, 4 iters
#pragma unroll
        for (int it = 0; it < 4; it++) {
            int i = tid + it * 128;
            int m = i >> 3, k4 = i & 7;
            float4 v = *(const float4*)&A[(size_t)(m0 + m) * K + k0 + k4 * 4];
            v.x = to_tf32(v.x); v.y = to_tf32(v.y);
            v.z = to_tf32(v.z); v.w = to_tf32(v.w);
            *(float4*)&As[m][k4 * 4] = v;
        }
        // B tile 32x128: 1024 float4, 8 iters
#pragma unroll
        for (int it = 0; it < 8; it++) {
            int i = tid + it * 128;
            int k = i >> 5, n4 = i & 31;
            float4 v = *(const float4*)&B[(size_t)(k0 + k) * N + n0 + n4 * 4];
            v.x = to_tf32(v.x); v.y = to_tf32(v.y);
            v.z = to_tf32(v.z); v.w = to_tf32(v.w);
            *(float4*)&Bs[k][n4 * 4] = v;
        }
        __syncthreads();

#pragma unroll
        for (int ks = 0; ks < 4; ks++) {
            int k8 = ks * 8;
            uint32_t a[2][4], b[8][2];
#pragma unroll
            for (int mi = 0; mi < 2; mi++) {
                int r = mw + 16 * mi + lq;
                a[mi][0] = __float_as_uint(As[r][k8 + lr]);
                a[mi][1] = __float_as_uint(As[r + 8][k8 + lr]);
                a[mi][2] = __float_as_uint(As[r][k8 + lr + 4]);
                a[mi][3] = __float_as_uint(As[r + 8][k8 + lr + 4]);
            }
#pragma unroll
            for (int ni = 0; ni < 8; ni++) {
                int c = nw + 8 * ni + lq;
                b[ni][0] = __float_as_uint(Bs[k8 + lr][c]);
                b[ni][1] = __float_as_uint(Bs[k8 + lr + 4][c]);
            }
#pragma unroll
            for (int mi = 0; mi < 2; mi++)
#pragma unroll
                for (int ni = 0; ni < 8; ni++)
                    mma_tf32(acc[mi][ni], a[mi], b[ni]);
        }
        __syncthreads();
    }

#pragma unroll
    for (int mi = 0; mi < 2; mi++) {
        int row0 = m0 + mw + 16 * mi + lq;
        float bi0 = bias[row0];
        float bi1 = bias[row0 + 8];
#pragma unroll
        for (int ni = 0; ni < 8; ni++) {
            int col = n0 + nw + 8 * ni + 2 * lr;
            float* p0 = &Cp[(size_t)row0 * N + col];
            float* p1 = &Cp[(size_t)(row0 + 8) * N + col];
            p0[0] = acc[mi][ni][0] + bi0;
            p0[1] = acc[mi][ni][1] + bi0;
            p1[0] = acc[mi][ni][2] + bi1;
            p1[1] = acc[mi][ni][3] + bi1;
        }
    }
}

// ---------------------------------------------------------------------------
// Tensor-core flash attention (unchanged from R12 passing version).
// ---------------------------------------------------------------------------
__global__ __launch_bounds__(256)
void attn_tc_kernel(const float* __restrict__ qkv,
                    float* __restrict__ aout) {
    extern __shared__ float sm[];
    float(*qs)[68]  = (float(*)[68])sm;                         // [t=128][c=64]
    float(*ks)[72]  = (float(*)[72])(sm + 128 * 68);            // [c=64][s=64]
    float(*vsT)[72] = (float(*)[72])(sm + 128 * 68 + 64 * 72);  // [s=64][c=64]
    float(*Ps)[68]  = (float(*)[68])(sm + 128 * 68 + 2 * 64 * 72); // [t=128][s=64]

    int bh = blockIdx.y;
    int t0 = blockIdx.x * 128;
    int b = bh >> 3, h = bh & 7;
    const float* base = qkv + ((size_t)b * 1536 + h * 192) * 1024;
    int tid = threadIdx.x;
    int lane = tid & 31;
    int warp = tid >> 5;
    int lq = lane >> 2;
    int lr = lane & 3;
    int rw = warp * 16;
    int r0 = rw + lq, r1 = rw + lq + 8;

#pragma unroll
    for (int it = 0; it < 32; it++) {
        int i = tid + it * 256;
        int c = i >> 7, t = i & 127;
        qs[t][c] = to_tf32(base[c * 1024 + t0 + t] * 0.125f);
    }

    float m0v = -INFINITY, m1v = -INFINITY, l0 = 0.f, l1 = 0.f;
    float accO[8][4] = {};
    __syncthreads();

    for (int s0 = 0; s0 < 1024; s0 += 64) {
#pragma unroll
        for (int it = 0; it < 4; it++) {
            int i = tid + it * 256;
            int c = i >> 4, s4 = (i & 15) * 4;
            float4 v = *(const float4*)&base[(64 + c) * 1024 + s0 + s4];
            v.x = to_tf32(v.x); v.y = to_tf32(v.y);
            v.z = to_tf32(v.z); v.w = to_tf32(v.w);
            *(float4*)&ks[c][s4] = v;
        }
#pragma unroll
        for (int it = 0; it < 16; it++) {
            int i = tid + it * 256;
            int c = i >> 6, s = i & 63;
            vsT[s][c] = to_tf32(base[(128 + c) * 1024 + s0 + s]);
        }
        __syncthreads();

        float accS[8][4] = {};
#pragma unroll
        for (int ks8 = 0; ks8 < 8; ks8++) {
            int k8 = ks8 * 8;
            uint32_t a[4];
            a[0] = __float_as_uint(qs[r0][k8 + lr]);
            a[1] = __float_as_uint(qs[r1][k8 + lr]);
            a[2] = __float_as_uint(qs[r0][k8 + lr + 4]);
            a[3] = __float_as_uint(qs[r1][k8 + lr + 4]);
#pragma unroll
            for (int ni = 0; ni < 8; ni++) {
                uint32_t bb[2];
                bb[0] = __float_as_uint(ks[k8 + lr][8 * ni + lq]);
                bb[1] = __float_as_uint(ks[k8 + lr + 4][8 * ni + lq]);
                mma_tf32(accS[ni], a, bb);
            }
        }

        float rm0 = -INFINITY, rm1 = -INFINITY;
#pragma unroll
        for (int ni = 0; ni < 8; ni++) {
            rm0 = fmaxf(rm0, fmaxf(accS[ni][0], accS[ni][1]));
            rm1 = fmaxf(rm1, fmaxf(accS[ni][2], accS[ni][3]));
        }
        rm0 = fmaxf(rm0, __shfl_xor_sync(0xffffffffu, rm0, 1));
        rm0 = fmaxf(rm0, __shfl_xor_sync(0xffffffffu, rm0, 2));
        rm1 = fmaxf(rm1, __shfl_xor_sync(0xffffffffu, rm1, 1));
        rm1 = fmaxf(rm1, __shfl_xor_sync(0xffffffffu, rm1, 2));
        float mn0 = fmaxf(m0v, rm0), mn1 = fmaxf(m1v, rm1);
        float corr0 = __expf(m0v - mn0), corr1 = __expf(m1v - mn1);
        float ps0 = 0.f, ps1 = 0.f;
#pragma unroll
        for (int ni = 0; ni < 8; ni++) {
            float p00 = __expf(accS[ni][0] - mn0);
            float p01 = __expf(accS[ni][1] - mn0);
            float p10 = __expf(accS[ni][2] - mn1);
            float p11 = __expf(accS[ni][3] - mn1);
            ps0 += p00 + p01;
            ps1 += p10 + p11;
            int c = 8 * ni + 2 * lr;
            Ps[r0][c]     = to_tf32(p00);
            Ps[r0][c + 1] = to_tf32(p01);
            Ps[r1][c]     = to_tf32(p10);
            Ps[r1][c + 1] = to_tf32(p11);
        }
        ps0 += __shfl_xor_sync(0xffffffffu, ps0, 1);
        ps0 += __shfl_xor_sync(0xffffffffu, ps0, 2);
        ps1 += __shfl_xor_sync(0xffffffffu, ps1, 1);
        ps1 += __shfl_xor_sync(0xffffffffu, ps1, 2);
        l0 = l0 * corr0 + ps0;
        l1 = l1 * corr1 + ps1;
        m0v = mn0; m1v = mn1;
#pragma unroll
        for (int ni = 0; ni < 8; ni++) {
            accO[ni][0] *= corr0; accO[ni][1] *= corr0;
            accO[ni][2] *= corr1; accO[ni][3] *= corr1;
        }
        __syncwarp();

#pragma unroll
        for (int ks8 = 0; ks8 < 8; ks8++) {
            int k8 = ks8 * 8;
            uint32_t a[4];
            a[0] = __float_as_uint(Ps[r0][k8 + lr]);
            a[1] = __float_as_uint(Ps[r1][k8 + lr]);
            a[2] = __float_as_uint(Ps[r0][k8 + lr + 4]);
            a[3] = __float_as_uint(Ps[r1][k8 + lr + 4]);
#pragma unroll
            for (int ni = 0; ni < 8; ni++) {
                uint32_t bb[2];
                bb[0] = __float_as_uint(vsT[k8 + lr][8 * ni + lq]);
                bb[1] = __float_as_uint(vsT[k8 + lr + 4][8 * ni + lq]);
                mma_tf32(accO[ni], a, bb);
            }
        }
        __syncthreads();
    }

    float inv0 = 1.0f / l0, inv1 = 1.0f / l1;
    float(*outS)[132] = (float(*)[132])sm;
#pragma unroll
    for (int ni = 0; ni < 8; ni++) {
        int c = 8 * ni + 2 * lr;
        outS[c][r0]     = accO[ni][0] * inv0;
        outS[c + 1][r0] = accO[ni][1] * inv0;
        outS[c][r1]     = accO[ni][2] * inv1;
        outS[c + 1][r1] = accO[ni][3] * inv1;
    }
    __syncthreads();

    size_t obase = ((size_t)b * 512 + h * 64) * 1024 + t0;
#pragma unroll
    for (int it = 0; it < 8; it++) {
        int i = tid + it * 256;
        int c = i >> 5, t4 = (i & 31) * 4;
        *(float4*)&aout[obase + (size_t)c * 1024 + t4] = *(const float4*)&outS[c][t4];
    }
}

// ---------------------------------------------------------------------------
// Launch
// ---------------------------------------------------------------------------
extern "C" void kernel_launch(void* const* d_in, const int* in_sizes, int n_in,
                              void* d_out, int out_size) {
    const float* x      = (const float*)d_in[0];
    const float* gn1_s  = (const float*)d_in[1];
    const float* gn1_b  = (const float*)d_in[2];
    const float* w_qkv  = (const float*)d_in[3];
    const float* b_qkv  = (const float*)d_in[4];
    const float* w_proj = (const float*)d_in[5];
    const float* b_proj = (const float*)d_in[6];
    const float* gn2_s  = (const float*)d_in[7];
    const float* gn2_b  = (const float*)d_in[8];
    float* out = (float*)d_out;

    float *hn, *qkv, *attn, *proj;
    cudaGetSymbolAddress((void**)&hn, g_hn);
    cudaGetSymbolAddress((void**)&qkv, g_qkv);
    cudaGetSymbolAddress((void**)&attn, g_attn);
    cudaGetSymbolAddress((void**)&proj, g_proj);

    const int ATTN_SMEM = (128 * 68 + 2 * 64 * 72 + 128 * 68) * 4;  // 106496 B
    cudaFuncSetAttribute(attn_tc_kernel, cudaFuncAttributeMaxDynamicSharedMemorySize,
                         ATTN_SMEM);

    // 1) GroupNorm1 (vectorized)
    gn_kernel<false><<<256, 1024>>>((const float4*)x, gn1_s, gn1_b, nullptr,
                                    (float4*)hn);
    // 2) qkv = W_qkv @ hn + b  (batched: 1536 x 1024 x 512, 8 batches)
    gemm_tf32_kernel<<<dim3(8, 24, 8), 128>>>(w_qkv, hn, b_qkv, qkv, 1536, 1024, 512);
    // 3) tensor-core flash attention per (bh, 128-row t-tile)
    attn_tc_kernel<<<dim3(8, 64), 256, ATTN_SMEM>>>(qkv, attn);
    // 4) proj = W_proj @ a + b  (512 x 1024 x 512, 8 batches)
    gemm_tf32_kernel<<<dim3(8, 8, 8), 128>>>(w_proj, attn, b_proj, proj, 512, 1024, 512);
    // 5) GroupNorm2 + residual (vectorized)
    gn_kernel<true><<<256, 1024>>>((const float4*)proj, gn2_s, gn2_b,
                                   (const float4*)x, (float4*)out);
}

// round 14
// speedup vs baseline: 1.3053x; 1.3053x over previous
#include <cuda_runtime.h>
#include <cuda_fp16.h>
#include <math.h>
#include <stdint.h>

// Problem constants
#define BATCH 8
#define CCH   512
#define NTOK  1024

// Scratch buffers (device globals — no allocation allowed)
__device__ float g_hn[BATCH * CCH * NTOK];        // GroupNorm1 output
__device__ float g_qkv[BATCH * 3 * CCH * NTOK];   // qkv conv output
__device__ float g_attn[BATCH * CCH * NTOK];      // attention output
__device__ float g_proj[BATCH * CCH * NTOK];      // proj conv output

// ---------------------------------------------------------------------------
// GroupNorm, vectorized: 1024 threads/block, one block per (b,g).
// ---------------------------------------------------------------------------
template <bool ADD_RES>
__global__ __launch_bounds__(1024)
void gn_kernel(const float4* __restrict__ x,
               const float* __restrict__ scale,
               const float* __restrict__ bias,
               const float4* __restrict__ resid,
               float4* __restrict__ out) {
    __shared__ float s_sum[32];
    __shared__ float s_sq[32];
    int blk = blockIdx.x;           // b*32 + g
    int g = blk & 31;
    size_t base = (size_t)blk * 4096;   // float4 units
    int tid = threadIdx.x;
    int lane = tid & 31, warp = tid >> 5;

    float sum = 0.f, sq = 0.f;
    float4 v[4];
#pragma unroll
    for (int it = 0; it < 4; it++) {
        v[it] = x[base + tid + it * 1024];
        sum += v[it].x + v[it].y + v[it].z + v[it].w;
        sq += v[it].x * v[it].x + v[it].y * v[it].y
            + v[it].z * v[it].z + v[it].w * v[it].w;
    }
#pragma unroll
    for (int o = 16; o; o >>= 1) {
        sum += __shfl_xor_sync(0xffffffffu, sum, o);
        sq  += __shfl_xor_sync(0xffffffffu, sq, o);
    }
    if (lane == 0) { s_sum[warp] = sum; s_sq[warp] = sq; }
    __syncthreads();
    if (warp == 0) {
        float a = s_sum[lane], b2 = s_sq[lane];
#pragma unroll
        for (int o = 16; o; o >>= 1) {
            a  += __shfl_xor_sync(0xffffffffu, a, o);
            b2 += __shfl_xor_sync(0xffffffffu, b2, o);
        }
        if (lane == 0) { s_sum[0] = a; s_sq[0] = b2; }
    }
    __syncthreads();
    float mean = s_sum[0] * (1.0f / 16384.0f);
    float var = s_sq[0] * (1.0f / 16384.0f) - mean * mean;
    float rstd = rsqrtf(var + 1e-5f);

#pragma unroll
    for (int it = 0; it < 4; it++) {
        int j = tid + it * 1024;
        int c = g * 16 + (j >> 8);
        float a = rstd * scale[c];
        float bb = bias[c] - mean * a;
        float4 o;
        o.x = v[it].x * a + bb;
        o.y = v[it].y * a + bb;
        o.z = v[it].z * a + bb;
        o.w = v[it].w * a + bb;
        if (ADD_RES) {
            float4 r = resid[base + j];
            o.x += r.x; o.y += r.y; o.z += r.z; o.w += r.w;
        }
        out[base + j] = o;
    }
}

// ---------------------------------------------------------------------------
// fp16 mma helpers
// ---------------------------------------------------------------------------
__device__ __forceinline__ uint32_t pack_h2(float lo, float hi) {
    __half2 h = __floats2half2_rn(lo, hi);
    return *reinterpret_cast<uint32_t*>(&h);
}

__device__ __forceinline__ void mma_f16(float* c, const uint32_t* a, const uint32_t* b) {
    asm volatile(
        "mma.sync.aligned.m16n8k16.row.col.f32.f16.f16.f32 "
        "{%0,%1,%2,%3}, {%4,%5,%6,%7}, {%8,%9}, {%0,%1,%2,%3};"
        : "+f"(c[0]), "+f"(c[1]), "+f"(c[2]), "+f"(c[3])
        : "r"(a[0]), "r"(a[1]), "r"(a[2]), "r"(a[3]), "r"(b[0]), "r"(b[1]));
}

// ---------------------------------------------------------------------------
// Batched fp16 tensor-core GEMM + bias (fp32 accumulate):
//   C[z][m][n] = sum_k A[m][k] * B[z][k][n] + bias[m]
// 128x128 block tile, BK=32, 256 threads, 8 warps (4m x 2n), warp tile 32x64.
// Operands stored as k-pair-packed half2 (uint32), stride 20 -> conflict-free
// fragment loads ((20*lq+lr) mod 32 bijective).
// ---------------------------------------------------------------------------
__global__ __launch_bounds__(256)
void gemm_f16_kernel(const float* __restrict__ A,
                     const float* __restrict__ Bm,
                     const float* __restrict__ bias,
                     float* __restrict__ Cm,
                     int M, int N, int K) {
    __shared__ uint32_t As2[128][20];   // [m][kpair] 10240 B
    __shared__ uint32_t Bs2[128][20];   // [n][kpair] 10240 B

    const float* B = Bm + (size_t)blockIdx.z * K * N;
    float* Cp = Cm + (size_t)blockIdx.z * M * N;
    int m0 = blockIdx.y * 128;
    int n0 = blockIdx.x * 128;
    int tid = threadIdx.x;
    int lane = tid & 31;
    int warp = tid >> 5;
    int mw = (warp >> 1) * 32;
    int nw = (warp & 1) * 64;
    int lq = lane >> 2;
    int lr = lane & 3;

    float acc[2][8][4] = {};

    for (int k0 = 0; k0 < K; k0 += 32) {
        // A tile 128x32: float4 along k, pack to half2 pairs
#pragma unroll
        for (int it = 0; it < 4; it++) {
            int i = tid + it * 256;
            int m = i >> 3, k4 = i & 7;
            float4 v = *(const float4*)&A[(size_t)(m0 + m) * K + k0 + k4 * 4];
            As2[m][k4 * 2]     = pack_h2(v.x, v.y);
            As2[m][k4 * 2 + 1] = pack_h2(v.z, v.w);
        }
        // B tile 32x128 -> [n][kpair]: scalar reads from 2 k-rows (coalesced in n)
#pragma unroll
        for (int it = 0; it < 8; it++) {
            int i = tid + it * 256;
            int n = i & 127, kp = i >> 7;
            float lo = B[(size_t)(k0 + 2 * kp) * N + n0 + n];
            float hi = B[(size_t)(k0 + 2 * kp + 1) * N + n0 + n];
            Bs2[n][kp] = pack_h2(lo, hi);
        }
        __syncthreads();

#pragma unroll
        for (int ks = 0; ks < 2; ks++) {
            int kb = ks * 8;        // kpair base (k16 per step)
            uint32_t a[2][4], b[8][2];
#pragma unroll
            for (int mi = 0; mi < 2; mi++) {
                int r = mw + 16 * mi + lq;
                a[mi][0] = As2[r][kb + lr];
                a[mi][1] = As2[r + 8][kb + lr];
                a[mi][2] = As2[r][kb + lr + 4];
                a[mi][3] = As2[r + 8][kb + lr + 4];
            }
#pragma unroll
            for (int ni = 0; ni < 8; ni++) {
                int c = nw + 8 * ni + lq;
                b[ni][0] = Bs2[c][kb + lr];
                b[ni][1] = Bs2[c][kb + lr + 4];
            }
#pragma unroll
            for (int mi = 0; mi < 2; mi++)
#pragma unroll
                for (int ni = 0; ni < 8; ni++)
                    mma_f16(acc[mi][ni], a[mi], b[ni]);
        }
        __syncthreads();
    }

    // Epilogue: bias + store (fragment layout same as m16n8k8)
#pragma unroll
    for (int mi = 0; mi < 2; mi++) {
        int row0 = m0 + mw + 16 * mi + lq;
        float bi0 = bias[row0];
        float bi1 = bias[row0 + 8];
#pragma unroll
        for (int ni = 0; ni < 8; ni++) {
            int col = n0 + nw + 8 * ni + 2 * lr;
            float* p0 = &Cp[(size_t)row0 * N + col];
            float* p1 = &Cp[(size_t)(row0 + 8) * N + col];
            p0[0] = acc[mi][ni][0] + bi0;
            p0[1] = acc[mi][ni][1] + bi0;
            p1[0] = acc[mi][ni][2] + bi1;
            p1[1] = acc[mi][ni][3] + bi1;
        }
    }
}

// ---------------------------------------------------------------------------
// fp16 tensor-core flash attention. Block = (bh, 128-row t-tile), 8 warps.
// Warp tile 16t x 64s; softmax in-warp. All operand tiles k-pair-packed
// half2, stride 36 uint32 (conflict-free fragment loads: (4*lq+lr) mod 32).
//   qs2[t][cpair], ks2[s][cpair], vs2[c][spair], Ps2[t][spair]
// scale^2 = 0.125 folded into q. fp32 accumulate + fp32 softmax.
// ---------------------------------------------------------------------------
__global__ __launch_bounds__(256)
void attn_f16_kernel(const float* __restrict__ qkv,
                     float* __restrict__ aout) {
    extern __shared__ uint32_t smu[];
    uint32_t(*qs2)[36] = (uint32_t(*)[36])smu;             // [128][36]
    uint32_t(*ks2)[36] = (uint32_t(*)[36])(smu + 4608);    // [64][36]
    uint32_t(*vs2)[36] = (uint32_t(*)[36])(smu + 6912);    // [64][36]
    uint32_t(*Ps2)[36] = (uint32_t(*)[36])(smu + 9216);    // [128][36]

    int bh = blockIdx.y;
    int t0 = blockIdx.x * 128;
    int b = bh >> 3, h = bh & 7;
    const float* base = qkv + ((size_t)b * 1536 + h * 192) * 1024;
    int tid = threadIdx.x;
    int lane = tid & 31;
    int warp = tid >> 5;
    int lq = lane >> 2;
    int lr = lane & 3;
    int rw = warp * 16;
    int r0 = rw + lq, r1 = rw + lq + 8;

    // Q -> qs2[t][cpair], fold scale^2 = 0.125
#pragma unroll
    for (int it = 0; it < 16; it++) {
        int i = tid + it * 256;
        int t = i & 127, cp = i >> 7;
        float lo = base[(2 * cp) * 1024 + t0 + t] * 0.125f;
        float hi = base[(2 * cp + 1) * 1024 + t0 + t] * 0.125f;
        qs2[t][cp] = pack_h2(lo, hi);
    }

    float m0v = -INFINITY, m1v = -INFINITY, l0 = 0.f, l1 = 0.f;
    float accO[8][4] = {};
    __syncthreads();

    for (int s0 = 0; s0 < 1024; s0 += 64) {
        // K -> ks2[s][cpair]
#pragma unroll
        for (int it = 0; it < 8; it++) {
            int i = tid + it * 256;
            int s = i & 63, cp = i >> 6;
            float lo = base[(64 + 2 * cp) * 1024 + s0 + s];
            float hi = base[(64 + 2 * cp + 1) * 1024 + s0 + s];
            ks2[s][cp] = pack_h2(lo, hi);
        }
        // V -> vs2[c][spair] (s contiguous in gmem: float4 -> 2x half2)
#pragma unroll
        for (int it = 0; it < 4; it++) {
            int i = tid + it * 256;
            int c = i >> 4, s4 = i & 15;
            float4 v = *(const float4*)&base[(128 + c) * 1024 + s0 + s4 * 4];
            vs2[c][2 * s4]     = pack_h2(v.x, v.y);
            vs2[c][2 * s4 + 1] = pack_h2(v.z, v.w);
        }
        __syncthreads();

        // S = Q K^T : contraction over c (64 = 4 k16 steps)
        float accS[8][4] = {};
#pragma unroll
        for (int ks = 0; ks < 4; ks++) {
            int kb = ks * 8;
            uint32_t a[4];
            a[0] = qs2[r0][kb + lr];
            a[1] = qs2[r1][kb + lr];
            a[2] = qs2[r0][kb + lr + 4];
            a[3] = qs2[r1][kb + lr + 4];
#pragma unroll
            for (int ni = 0; ni < 8; ni++) {
                uint32_t bb[2];
                bb[0] = ks2[8 * ni + lq][kb + lr];
                bb[1] = ks2[8 * ni + lq][kb + lr + 4];
                mma_f16(accS[ni], a, bb);
            }
        }

        // Online softmax (rows r0: c0,c1; r1: c2,c3; row spans 4 lanes)
        float rm0 = -INFINITY, rm1 = -INFINITY;
#pragma unroll
        for (int ni = 0; ni < 8; ni++) {
            rm0 = fmaxf(rm0, fmaxf(accS[ni][0], accS[ni][1]));
            rm1 = fmaxf(rm1, fmaxf(accS[ni][2], accS[ni][3]));
        }
        rm0 = fmaxf(rm0, __shfl_xor_sync(0xffffffffu, rm0, 1));
        rm0 = fmaxf(rm0, __shfl_xor_sync(0xffffffffu, rm0, 2));
        rm1 = fmaxf(rm1, __shfl_xor_sync(0xffffffffu, rm1, 1));
        rm1 = fmaxf(rm1, __shfl_xor_sync(0xffffffffu, rm1, 2));
        float mn0 = fmaxf(m0v, rm0), mn1 = fmaxf(m1v, rm1);
        float corr0 = __expf(m0v - mn0), corr1 = __expf(m1v - mn1);
        float ps0 = 0.f, ps1 = 0.f;
#pragma unroll
        for (int ni = 0; ni < 8; ni++) {
            float p00 = __expf(accS[ni][0] - mn0);
            float p01 = __expf(accS[ni][1] - mn0);
            float p10 = __expf(accS[ni][2] - mn1);
            float p11 = __expf(accS[ni][3] - mn1);
            ps0 += p00 + p01;
            ps1 += p10 + p11;
            Ps2[r0][4 * ni + lr] = pack_h2(p00, p01);
            Ps2[r1][4 * ni + lr] = pack_h2(p10, p11);
        }
        ps0 += __shfl_xor_sync(0xffffffffu, ps0, 1);
        ps0 += __shfl_xor_sync(0xffffffffu, ps0, 2);
        ps1 += __shfl_xor_sync(0xffffffffu, ps1, 1);
        ps1 += __shfl_xor_sync(0xffffffffu, ps1, 2);
        l0 = l0 * corr0 + ps0;
        l1 = l1 * corr1 + ps1;
        m0v = mn0; m1v = mn1;
#pragma unroll
        for (int ni = 0; ni < 8; ni++) {
            accO[ni][0] *= corr0; accO[ni][1] *= corr0;
            accO[ni][2] *= corr1; accO[ni][3] *= corr1;
        }
        __syncwarp();   // Ps2 rows read only by the writing warp

        // O += P V : contraction over s (64 = 4 k16 steps)
#pragma unroll
        for (int ks = 0; ks < 4; ks++) {
            int kb = ks * 8;
            uint32_t a[4];
            a[0] = Ps2[r0][kb + lr];
            a[1] = Ps2[r1][kb + lr];
            a[2] = Ps2[r0][kb + lr + 4];
            a[3] = Ps2[r1][kb + lr + 4];
#pragma unroll
            for (int ni = 0; ni < 8; ni++) {
                uint32_t bb[2];
                bb[0] = vs2[8 * ni + lq][kb + lr];
                bb[1] = vs2[8 * ni + lq][kb + lr + 4];
                mma_f16(accO[ni], a, bb);
            }
        }
        __syncthreads();   // ks2/vs2 consumed before next-iter overwrite
    }

    // Epilogue: normalize, stage transposed [c][t] (reuse smem), store.
    float inv0 = 1.0f / l0, inv1 = 1.0f / l1;
    float(*outS)[132] = (float(*)[132])smu;   // 64 x 132 floats = 33792 B
    __syncthreads();
#pragma unroll
    for (int ni = 0; ni < 8; ni++) {
        int c = 8 * ni + 2 * lr;
        outS[c][r0]     = accO[ni][0] * inv0;
        outS[c + 1][r0] = accO[ni][1] * inv0;
        outS[c][r1]     = accO[ni][2] * inv1;
        outS[c + 1][r1] = accO[ni][3] * inv1;
    }
    __syncthreads();

    size_t obase = ((size_t)b * 512 + h * 64) * 1024 + t0;
#pragma unroll
    for (int it = 0; it < 8; it++) {
        int i = tid + it * 256;
        int c = i >> 5, t4 = (i & 31) * 4;
        *(float4*)&aout[obase + (size_t)c * 1024 + t4] = *(const float4*)&outS[c][t4];
    }
}

// ---------------------------------------------------------------------------
// Launch
// ---------------------------------------------------------------------------
extern "C" void kernel_launch(void* const* d_in, const int* in_sizes, int n_in,
                              void* d_out, int out_size) {
    const float* x      = (const float*)d_in[0];
    const float* gn1_s  = (const float*)d_in[1];
    const float* gn1_b  = (const float*)d_in[2];
    const float* w_qkv  = (const float*)d_in[3];
    const float* b_qkv  = (const float*)d_in[4];
    const float* w_proj = (const float*)d_in[5];
    const float* b_proj = (const float*)d_in[6];
    const float* gn2_s  = (const float*)d_in[7];
    const float* gn2_b  = (const float*)d_in[8];
    float* out = (float*)d_out;

    float *hn, *qkv, *attn, *proj;
    cudaGetSymbolAddress((void**)&hn, g_hn);
    cudaGetSymbolAddress((void**)&qkv, g_qkv);
    cudaGetSymbolAddress((void**)&attn, g_attn);
    cudaGetSymbolAddress((void**)&proj, g_proj);

    const int ATTN_SMEM = (2 * 128 * 36 + 2 * 64 * 36) * 4;  // 55296 B
    cudaFuncSetAttribute(attn_f16_kernel, cudaFuncAttributeMaxDynamicSharedMemorySize,
                         ATTN_SMEM);

    // 1) GroupNorm1 (vectorized)
    gn_kernel<false><<<256, 1024>>>((const float4*)x, gn1_s, gn1_b, nullptr,
                                    (float4*)hn);
    // 2) qkv = W_qkv @ hn + b  (batched: 1536 x 1024 x 512, 8 batches)
    gemm_f16_kernel<<<dim3(8, 12, 8), 256>>>(w_qkv, hn, b_qkv, qkv, 1536, 1024, 512);
    // 3) fp16 tensor-core flash attention per (bh, 128-row t-tile)
    attn_f16_kernel<<<dim3(8, 64), 256, ATTN_SMEM>>>(qkv, attn);
    // 4) proj = W_proj @ a + b  (512 x 1024 x 512, 8 batches)
    gemm_f16_kernel<<<dim3(8, 4, 8), 256>>>(w_proj, attn, b_proj, proj, 512, 1024, 512);
    // 5) GroupNorm2 + residual (vectorized)
    gn_kernel<true><<<256, 1024>>>((const float4*)proj, gn2_s, gn2_b,
                                   (const float4*)x, (float4*)out);
}

// round 15
// speedup vs baseline: 1.3616x; 1.0431x over previous
#include <cuda_runtime.h>
#include <cuda_fp16.h>
#include <math.h>
#include <stdint.h>

// Problem constants
#define BATCH 8
#define CCH   512
#define NTOK  1024

// Scratch buffers (device globals — no allocation allowed)
__device__ float g_hn[BATCH * CCH * NTOK];        // GroupNorm1 output
__device__ float g_qkv[BATCH * 3 * CCH * NTOK];   // qkv conv output
__device__ float g_attn[BATCH * CCH * NTOK];      // attention output
__device__ float g_proj[BATCH * CCH * NTOK];      // proj conv output

// ---------------------------------------------------------------------------
// GroupNorm, vectorized: 1024 threads/block, one block per (b,g).
// ---------------------------------------------------------------------------
template <bool ADD_RES>
__global__ __launch_bounds__(1024)
void gn_kernel(const float4* __restrict__ x,
               const float* __restrict__ scale,
               const float* __restrict__ bias,
               const float4* __restrict__ resid,
               float4* __restrict__ out) {
    __shared__ float s_sum[32];
    __shared__ float s_sq[32];
    int blk = blockIdx.x;           // b*32 + g
    int g = blk & 31;
    size_t base = (size_t)blk * 4096;   // float4 units
    int tid = threadIdx.x;
    int lane = tid & 31, warp = tid >> 5;

    float sum = 0.f, sq = 0.f;
    float4 v[4];
#pragma unroll
    for (int it = 0; it < 4; it++) {
        v[it] = x[base + tid + it * 1024];
        sum += v[it].x + v[it].y + v[it].z + v[it].w;
        sq += v[it].x * v[it].x + v[it].y * v[it].y
            + v[it].z * v[it].z + v[it].w * v[it].w;
    }
#pragma unroll
    for (int o = 16; o; o >>= 1) {
        sum += __shfl_xor_sync(0xffffffffu, sum, o);
        sq  += __shfl_xor_sync(0xffffffffu, sq, o);
    }
    if (lane == 0) { s_sum[warp] = sum; s_sq[warp] = sq; }
    __syncthreads();
    if (warp == 0) {
        float a = s_sum[lane], b2 = s_sq[lane];
#pragma unroll
        for (int o = 16; o; o >>= 1) {
            a  += __shfl_xor_sync(0xffffffffu, a, o);
            b2 += __shfl_xor_sync(0xffffffffu, b2, o);
        }
        if (lane == 0) { s_sum[0] = a; s_sq[0] = b2; }
    }
    __syncthreads();
    float mean = s_sum[0] * (1.0f / 16384.0f);
    float var = s_sq[0] * (1.0f / 16384.0f) - mean * mean;
    float rstd = rsqrtf(var + 1e-5f);

#pragma unroll
    for (int it = 0; it < 4; it++) {
        int j = tid + it * 1024;
        int c = g * 16 + (j >> 8);
        float a = rstd * scale[c];
        float bb = bias[c] - mean * a;
        float4 o;
        o.x = v[it].x * a + bb;
        o.y = v[it].y * a + bb;
        o.z = v[it].z * a + bb;
        o.w = v[it].w * a + bb;
        if (ADD_RES) {
            float4 r = resid[base + j];
            o.x += r.x; o.y += r.y; o.z += r.z; o.w += r.w;
        }
        out[base + j] = o;
    }
}

// ---------------------------------------------------------------------------
// fp16 mma helpers
// ---------------------------------------------------------------------------
__device__ __forceinline__ uint32_t pack_h2(float lo, float hi) {
    __half2 h = __floats2half2_rn(lo, hi);
    return *reinterpret_cast<uint32_t*>(&h);
}

__device__ __forceinline__ void mma_f16(float* c, const uint32_t* a, const uint32_t* b) {
    asm volatile(
        "mma.sync.aligned.m16n8k16.row.col.f32.f16.f16.f32 "
        "{%0,%1,%2,%3}, {%4,%5,%6,%7}, {%8,%9}, {%0,%1,%2,%3};"
        : "+f"(c[0]), "+f"(c[1]), "+f"(c[2]), "+f"(c[3])
        : "r"(a[0]), "r"(a[1]), "r"(a[2]), "r"(a[3]), "r"(b[0]), "r"(b[1]));
}

// ---------------------------------------------------------------------------
// Batched fp16 tensor-core GEMM + bias (fp32 accumulate):
//   C[z][m][n] = sum_k A[m][k] * B[z][k][n] + bias[m]
// 128x128 block tile, BK=32, 256 threads, 8 warps (4m x 2n), warp tile 32x64.
// k-pair-packed half2 smem (stride 20 -> conflict-free fragment loads).
// __launch_bounds__(256,2): cap regs at 128 so 2 blocks/SM co-reside.
// ---------------------------------------------------------------------------
__global__ __launch_bounds__(256, 2)
void gemm_f16_kernel(const float* __restrict__ A,
                     const float* __restrict__ Bm,
                     const float* __restrict__ bias,
                     float* __restrict__ Cm,
                     int M, int N, int K) {
    __shared__ uint32_t As2[128][20];   // [m][kpair] 10240 B
    __shared__ uint32_t Bs2[128][20];   // [n][kpair] 10240 B

    const float* B = Bm + (size_t)blockIdx.z * K * N;
    float* Cp = Cm + (size_t)blockIdx.z * M * N;
    int m0 = blockIdx.y * 128;
    int n0 = blockIdx.x * 128;
    int tid = threadIdx.x;
    int lane = tid & 31;
    int warp = tid >> 5;
    int mw = (warp >> 1) * 32;
    int nw = (warp & 1) * 64;
    int lq = lane >> 2;
    int lr = lane & 3;

    float acc[2][8][4] = {};

    for (int k0 = 0; k0 < K; k0 += 32) {
        // A tile 128x32: float4 along k, pack to half2 pairs
#pragma unroll
        for (int it = 0; it < 4; it++) {
            int i = tid + it * 256;
            int m = i >> 3, k4 = i & 7;
            float4 v = *(const float4*)&A[(size_t)(m0 + m) * K + k0 + k4 * 4];
            As2[m][k4 * 2]     = pack_h2(v.x, v.y);
            As2[m][k4 * 2 + 1] = pack_h2(v.z, v.w);
        }
        // B tile 32x128 -> [n][kpair]: scalar reads from 2 k-rows (coalesced in n)
#pragma unroll
        for (int it = 0; it < 8; it++) {
            int i = tid + it * 256;
            int n = i & 127, kp = i >> 7;
            float lo = B[(size_t)(k0 + 2 * kp) * N + n0 + n];
            float hi = B[(size_t)(k0 + 2 * kp + 1) * N + n0 + n];
            Bs2[n][kp] = pack_h2(lo, hi);
        }
        __syncthreads();

#pragma unroll
        for (int ks = 0; ks < 2; ks++) {
            int kb = ks * 8;        // kpair base (k16 per step)
            uint32_t a[2][4], b[8][2];
#pragma unroll
            for (int mi = 0; mi < 2; mi++) {
                int r = mw + 16 * mi + lq;
                a[mi][0] = As2[r][kb + lr];
                a[mi][1] = As2[r + 8][kb + lr];
                a[mi][2] = As2[r][kb + lr + 4];
                a[mi][3] = As2[r + 8][kb + lr + 4];
            }
#pragma unroll
            for (int ni = 0; ni < 8; ni++) {
                int c = nw + 8 * ni + lq;
                b[ni][0] = Bs2[c][kb + lr];
                b[ni][1] = Bs2[c][kb + lr + 4];
            }
#pragma unroll
            for (int mi = 0; mi < 2; mi++)
#pragma unroll
                for (int ni = 0; ni < 8; ni++)
                    mma_f16(acc[mi][ni], a[mi], b[ni]);
        }
        __syncthreads();
    }

    // Epilogue: bias + store
#pragma unroll
    for (int mi = 0; mi < 2; mi++) {
        int row0 = m0 + mw + 16 * mi + lq;
        float bi0 = bias[row0];
        float bi1 = bias[row0 + 8];
#pragma unroll
        for (int ni = 0; ni < 8; ni++) {
            int col = n0 + nw + 8 * ni + 2 * lr;
            float* p0 = &Cp[(size_t)row0 * N + col];
            float* p1 = &Cp[(size_t)(row0 + 8) * N + col];
            p0[0] = acc[mi][ni][0] + bi0;
            p0[1] = acc[mi][ni][1] + bi0;
            p1[0] = acc[mi][ni][2] + bi1;
            p1[1] = acc[mi][ni][3] + bi1;
        }
    }
}

// ---------------------------------------------------------------------------
// fp16 tensor-core flash attention (structure unchanged from R14);
// __launch_bounds__(256,2) to allow 2 blocks/SM.
// ---------------------------------------------------------------------------
__global__ __launch_bounds__(256, 2)
void attn_f16_kernel(const float* __restrict__ qkv,
                     float* __restrict__ aout) {
    extern __shared__ uint32_t smu[];
    uint32_t(*qs2)[36] = (uint32_t(*)[36])smu;             // [128][36]
    uint32_t(*ks2)[36] = (uint32_t(*)[36])(smu + 4608);    // [64][36]
    uint32_t(*vs2)[36] = (uint32_t(*)[36])(smu + 6912);    // [64][36]
    uint32_t(*Ps2)[36] = (uint32_t(*)[36])(smu + 9216);    // [128][36]

    int bh = blockIdx.y;
    int t0 = blockIdx.x * 128;
    int b = bh >> 3, h = bh & 7;
    const float* base = qkv + ((size_t)b * 1536 + h * 192) * 1024;
    int tid = threadIdx.x;
    int lane = tid & 31;
    int warp = tid >> 5;
    int lq = lane >> 2;
    int lr = lane & 3;
    int rw = warp * 16;
    int r0 = rw + lq, r1 = rw + lq + 8;

    // Q -> qs2[t][cpair], fold scale^2 = 0.125
#pragma unroll
    for (int it = 0; it < 16; it++) {
        int i = tid + it * 256;
        int t = i & 127, cp = i >> 7;
        float lo = base[(2 * cp) * 1024 + t0 + t] * 0.125f;
        float hi = base[(2 * cp + 1) * 1024 + t0 + t] * 0.125f;
        qs2[t][cp] = pack_h2(lo, hi);
    }

    float m0v = -INFINITY, m1v = -INFINITY, l0 = 0.f, l1 = 0.f;
    float accO[8][4] = {};
    __syncthreads();

    for (int s0 = 0; s0 < 1024; s0 += 64) {
        // K -> ks2[s][cpair]
#pragma unroll
        for (int it = 0; it < 8; it++) {
            int i = tid + it * 256;
            int s = i & 63, cp = i >> 6;
            float lo = base[(64 + 2 * cp) * 1024 + s0 + s];
            float hi = base[(64 + 2 * cp + 1) * 1024 + s0 + s];
            ks2[s][cp] = pack_h2(lo, hi);
        }
        // V -> vs2[c][spair]
#pragma unroll
        for (int it = 0; it < 4; it++) {
            int i = tid + it * 256;
            int c = i >> 4, s4 = i & 15;
            float4 v = *(const float4*)&base[(128 + c) * 1024 + s0 + s4 * 4];
            vs2[c][2 * s4]     = pack_h2(v.x, v.y);
            vs2[c][2 * s4 + 1] = pack_h2(v.z, v.w);
        }
        __syncthreads();

        // S = Q K^T
        float accS[8][4] = {};
#pragma unroll
        for (int ks = 0; ks < 4; ks++) {
            int kb = ks * 8;
            uint32_t a[4];
            a[0] = qs2[r0][kb + lr];
            a[1] = qs2[r1][kb + lr];
            a[2] = qs2[r0][kb + lr + 4];
            a[3] = qs2[r1][kb + lr + 4];
#pragma unroll
            for (int ni = 0; ni < 8; ni++) {
                uint32_t bb[2];
                bb[0] = ks2[8 * ni + lq][kb + lr];
                bb[1] = ks2[8 * ni + lq][kb + lr + 4];
                mma_f16(accS[ni], a, bb);
            }
        }

        // Online softmax
        float rm0 = -INFINITY, rm1 = -INFINITY;
#pragma unroll
        for (int ni = 0; ni < 8; ni++) {
            rm0 = fmaxf(rm0, fmaxf(accS[ni][0], accS[ni][1]));
            rm1 = fmaxf(rm1, fmaxf(accS[ni][2], accS[ni][3]));
        }
        rm0 = fmaxf(rm0, __shfl_xor_sync(0xffffffffu, rm0, 1));
        rm0 = fmaxf(rm0, __shfl_xor_sync(0xffffffffu, rm0, 2));
        rm1 = fmaxf(rm1, __shfl_xor_sync(0xffffffffu, rm1, 1));
        rm1 = fmaxf(rm1, __shfl_xor_sync(0xffffffffu, rm1, 2));
        float mn0 = fmaxf(m0v, rm0), mn1 = fmaxf(m1v, rm1);
        float corr0 = __expf(m0v - mn0), corr1 = __expf(m1v - mn1);
        float ps0 = 0.f, ps1 = 0.f;
#pragma unroll
        for (int ni = 0; ni < 8; ni++) {
            float p00 = __expf(accS[ni][0] - mn0);
            float p01 = __expf(accS[ni][1] - mn0);
            float p10 = __expf(accS[ni][2] - mn1);
            float p11 = __expf(accS[ni][3] - mn1);
            ps0 += p00 + p01;
            ps1 += p10 + p11;
            Ps2[r0][4 * ni + lr] = pack_h2(p00, p01);
            Ps2[r1][4 * ni + lr] = pack_h2(p10, p11);
        }
        ps0 += __shfl_xor_sync(0xffffffffu, ps0, 1);
        ps0 += __shfl_xor_sync(0xffffffffu, ps0, 2);
        ps1 += __shfl_xor_sync(0xffffffffu, ps1, 1);
        ps1 += __shfl_xor_sync(0xffffffffu, ps1, 2);
        l0 = l0 * corr0 + ps0;
        l1 = l1 * corr1 + ps1;
        m0v = mn0; m1v = mn1;
#pragma unroll
        for (int ni = 0; ni < 8; ni++) {
            accO[ni][0] *= corr0; accO[ni][1] *= corr0;
            accO[ni][2] *= corr1; accO[ni][3] *= corr1;
        }
        __syncwarp();

        // O += P V
#pragma unroll
        for (int ks = 0; ks < 4; ks++) {
            int kb = ks * 8;
            uint32_t a[4];
            a[0] = Ps2[r0][kb + lr];
            a[1] = Ps2[r1][kb + lr];
            a[2] = Ps2[r0][kb + lr + 4];
            a[3] = Ps2[r1][kb + lr + 4];
#pragma unroll
            for (int ni = 0; ni < 8; ni++) {
                uint32_t bb[2];
                bb[0] = vs2[8 * ni + lq][kb + lr];
                bb[1] = vs2[8 * ni + lq][kb + lr + 4];
                mma_f16(accO[ni], a, bb);
            }
        }
        __syncthreads();
    }

    // Epilogue: normalize, stage transposed [c][t], store.
    float inv0 = 1.0f / l0, inv1 = 1.0f / l1;
    float(*outS)[132] = (float(*)[132])smu;   // 64 x 132 floats
    __syncthreads();
#pragma unroll
    for (int ni = 0; ni < 8; ni++) {
        int c = 8 * ni + 2 * lr;
        outS[c][r0]     = accO[ni][0] * inv0;
        outS[c + 1][r0] = accO[ni][1] * inv0;
        outS[c][r1]     = accO[ni][2] * inv1;
        outS[c + 1][r1] = accO[ni][3] * inv1;
    }
    __syncthreads();

    size_t obase = ((size_t)b * 512 + h * 64) * 1024 + t0;
#pragma unroll
    for (int it = 0; it < 8; it++) {
        int i = tid + it * 256;
        int c = i >> 5, t4 = (i & 31) * 4;
        *(float4*)&aout[obase + (size_t)c * 1024 + t4] = *(const float4*)&outS[c][t4];
    }
}

// ---------------------------------------------------------------------------
// Launch
// ---------------------------------------------------------------------------
extern "C" void kernel_launch(void* const* d_in, const int* in_sizes, int n_in,
                              void* d_out, int out_size) {
    const float* x      = (const float*)d_in[0];
    const float* gn1_s  = (const float*)d_in[1];
    const float* gn1_b  = (const float*)d_in[2];
    const float* w_qkv  = (const float*)d_in[3];
    const float* b_qkv  = (const float*)d_in[4];
    const float* w_proj = (const float*)d_in[5];
    const float* b_proj = (const float*)d_in[6];
    const float* gn2_s  = (const float*)d_in[7];
    const float* gn2_b  = (const float*)d_in[8];
    float* out = (float*)d_out;

    float *hn, *qkv, *attn, *proj;
    cudaGetSymbolAddress((void**)&hn, g_hn);
    cudaGetSymbolAddress((void**)&qkv, g_qkv);
    cudaGetSymbolAddress((void**)&attn, g_attn);
    cudaGetSymbolAddress((void**)&proj, g_proj);

    const int ATTN_SMEM = (2 * 128 * 36 + 2 * 64 * 36) * 4;  // 55296 B
    cudaFuncSetAttribute(attn_f16_kernel, cudaFuncAttributeMaxDynamicSharedMemorySize,
                         ATTN_SMEM);

    // 1) GroupNorm1 (vectorized)
    gn_kernel<false><<<256, 1024>>>((const float4*)x, gn1_s, gn1_b, nullptr,
                                    (float4*)hn);
    // 2) qkv = W_qkv @ hn + b  (batched: 1536 x 1024 x 512, 8 batches)
    gemm_f16_kernel<<<dim3(8, 12, 8), 256>>>(w_qkv, hn, b_qkv, qkv, 1536, 1024, 512);
    // 3) fp16 tensor-core flash attention per (bh, 128-row t-tile)
    attn_f16_kernel<<<dim3(8, 64), 256, ATTN_SMEM>>>(qkv, attn);
    // 4) proj = W_proj @ a + b  (512 x 1024 x 512, 8 batches)
    gemm_f16_kernel<<<dim3(8, 4, 8), 256>>>(w_proj, attn, b_proj, proj, 512, 1024, 512);
    // 5) GroupNorm2 + residual (vectorized)
    gn_kernel<true><<<256, 1024>>>((const float4*)proj, gn2_s, gn2_b,
                                   (const float4*)x, (float4*)out);
}

// round 16
// speedup vs baseline: 1.6078x; 1.1809x over previous
#include <cuda_runtime.h>
#include <cuda_fp16.h>
#include <math.h>
#include <stdint.h>

// Problem constants
#define BATCH 8
#define CCH   512
#define NTOK  1024

// Scratch buffers (device globals — no allocation allowed)
__device__ float g_hn[BATCH * CCH * NTOK];        // GroupNorm1 output
__device__ float g_qkv[BATCH * 3 * CCH * NTOK];   // qkv conv output
__device__ float g_attn[BATCH * CCH * NTOK];      // attention output
__device__ float g_proj[BATCH * CCH * NTOK];      // proj conv output

// ---------------------------------------------------------------------------
// GroupNorm, vectorized: 1024 threads/block, one block per (b,g).
// ---------------------------------------------------------------------------
template <bool ADD_RES>
__global__ __launch_bounds__(1024)
void gn_kernel(const float4* __restrict__ x,
               const float* __restrict__ scale,
               const float* __restrict__ bias,
               const float4* __restrict__ resid,
               float4* __restrict__ out) {
    __shared__ float s_sum[32];
    __shared__ float s_sq[32];
    int blk = blockIdx.x;           // b*32 + g
    int g = blk & 31;
    size_t base = (size_t)blk * 4096;   // float4 units
    int tid = threadIdx.x;
    int lane = tid & 31, warp = tid >> 5;

    float sum = 0.f, sq = 0.f;
    float4 v[4];
#pragma unroll
    for (int it = 0; it < 4; it++) {
        v[it] = x[base + tid + it * 1024];
        sum += v[it].x + v[it].y + v[it].z + v[it].w;
        sq += v[it].x * v[it].x + v[it].y * v[it].y
            + v[it].z * v[it].z + v[it].w * v[it].w;
    }
#pragma unroll
    for (int o = 16; o; o >>= 1) {
        sum += __shfl_xor_sync(0xffffffffu, sum, o);
        sq  += __shfl_xor_sync(0xffffffffu, sq, o);
    }
    if (lane == 0) { s_sum[warp] = sum; s_sq[warp] = sq; }
    __syncthreads();
    if (warp == 0) {
        float a = s_sum[lane], b2 = s_sq[lane];
#pragma unroll
        for (int o = 16; o; o >>= 1) {
            a  += __shfl_xor_sync(0xffffffffu, a, o);
            b2 += __shfl_xor_sync(0xffffffffu, b2, o);
        }
        if (lane == 0) { s_sum[0] = a; s_sq[0] = b2; }
    }
    __syncthreads();
    float mean = s_sum[0] * (1.0f / 16384.0f);
    float var = s_sq[0] * (1.0f / 16384.0f) - mean * mean;
    float rstd = rsqrtf(var + 1e-5f);

#pragma unroll
    for (int it = 0; it < 4; it++) {
        int j = tid + it * 1024;
        int c = g * 16 + (j >> 8);
        float a = rstd * scale[c];
        float bb = bias[c] - mean * a;
        float4 o;
        o.x = v[it].x * a + bb;
        o.y = v[it].y * a + bb;
        o.z = v[it].z * a + bb;
        o.w = v[it].w * a + bb;
        if (ADD_RES) {
            float4 r = resid[base + j];
            o.x += r.x; o.y += r.y; o.z += r.z; o.w += r.w;
        }
        out[base + j] = o;
    }
}

// ---------------------------------------------------------------------------
// fp16 mma helpers
// ---------------------------------------------------------------------------
__device__ __forceinline__ uint32_t pack_h2(float lo, float hi) {
    __half2 h = __floats2half2_rn(lo, hi);
    return *reinterpret_cast<uint32_t*>(&h);
}

__device__ __forceinline__ void mma_f16(float* c, const uint32_t* a, const uint32_t* b) {
    asm volatile(
        "mma.sync.aligned.m16n8k16.row.col.f32.f16.f16.f32 "
        "{%0,%1,%2,%3}, {%4,%5,%6,%7}, {%8,%9}, {%0,%1,%2,%3};"
        : "+f"(c[0]), "+f"(c[1]), "+f"(c[2]), "+f"(c[3])
        : "r"(a[0]), "r"(a[1]), "r"(a[2]), "r"(a[3]), "r"(b[0]), "r"(b[1]));
}

// ---------------------------------------------------------------------------
// Batched fp16 tensor-core GEMM + bias (fp32 accumulate):
//   C[z][m][n] = sum_k A[m][k] * B[z][k][n] + bias[m]
// 128x128 block tile, BK=32, 256 threads, 8 warps (4m x 2n), warp tile 32x64.
// As2[m][kpair] stride 20 (reads (4lq+lr) bijective -> conflict-free).
// Bs2[kpair][n] stride 136 (reads (8lr+lq) bijective -> conflict-free;
//   fills are float4 gmem loads + uint4 smem stores, conflict-free).
// ---------------------------------------------------------------------------
__global__ __launch_bounds__(256, 2)
void gemm_f16_kernel(const float* __restrict__ A,
                     const float* __restrict__ Bm,
                     const float* __restrict__ bias,
                     float* __restrict__ Cm,
                     int M, int N, int K) {
    __shared__ uint32_t As2[128][20];   // [m][kpair] 10240 B
    __shared__ uint32_t Bs2[16][136];   // [kpair][n]  8704 B

    const float* B = Bm + (size_t)blockIdx.z * K * N;
    float* Cp = Cm + (size_t)blockIdx.z * M * N;
    int m0 = blockIdx.y * 128;
    int n0 = blockIdx.x * 128;
    int tid = threadIdx.x;
    int lane = tid & 31;
    int warp = tid >> 5;
    int mw = (warp >> 1) * 32;
    int nw = (warp & 1) * 64;
    int lq = lane >> 2;
    int lr = lane & 3;

    float acc[2][8][4] = {};

    for (int k0 = 0; k0 < K; k0 += 32) {
        // A tile 128x32: float4 along k, uint2 pack-store
#pragma unroll
        for (int it = 0; it < 4; it++) {
            int i = tid + it * 256;
            int m = i >> 3, k4 = i & 7;
            float4 v = *(const float4*)&A[(size_t)(m0 + m) * K + k0 + k4 * 4];
            uint2 st;
            st.x = pack_h2(v.x, v.y);
            st.y = pack_h2(v.z, v.w);
            *(uint2*)&As2[m][k4 * 2] = st;
        }
        // B tile 32x128 -> [kpair][n]: 2 float4 loads (rows 2kp, 2kp+1) + uint4 store
#pragma unroll
        for (int it = 0; it < 2; it++) {
            int i = tid + it * 256;
            int kp = i >> 5, n4 = (i & 31) * 4;
            const float* bp = &B[(size_t)(k0 + 2 * kp) * N + n0 + n4];
            float4 lo = *(const float4*)bp;
            float4 hi = *(const float4*)(bp + N);
            uint4 st;
            st.x = pack_h2(lo.x, hi.x);
            st.y = pack_h2(lo.y, hi.y);
            st.z = pack_h2(lo.z, hi.z);
            st.w = pack_h2(lo.w, hi.w);
            *(uint4*)&Bs2[kp][n4] = st;
        }
        __syncthreads();

#pragma unroll
        for (int ks = 0; ks < 2; ks++) {
            int kb = ks * 8;        // kpair base (k16 per step)
            uint32_t a[2][4], b[8][2];
#pragma unroll
            for (int mi = 0; mi < 2; mi++) {
                int r = mw + 16 * mi + lq;
                a[mi][0] = As2[r][kb + lr];
                a[mi][1] = As2[r + 8][kb + lr];
                a[mi][2] = As2[r][kb + lr + 4];
                a[mi][3] = As2[r + 8][kb + lr + 4];
            }
#pragma unroll
            for (int ni = 0; ni < 8; ni++) {
                int c = nw + 8 * ni + lq;
                b[ni][0] = Bs2[kb + lr][c];
                b[ni][1] = Bs2[kb + lr + 4][c];
            }
#pragma unroll
            for (int mi = 0; mi < 2; mi++)
#pragma unroll
                for (int ni = 0; ni < 8; ni++)
                    mma_f16(acc[mi][ni], a[mi], b[ni]);
        }
        __syncthreads();
    }

    // Epilogue: bias + store
#pragma unroll
    for (int mi = 0; mi < 2; mi++) {
        int row0 = m0 + mw + 16 * mi + lq;
        float bi0 = bias[row0];
        float bi1 = bias[row0 + 8];
#pragma unroll
        for (int ni = 0; ni < 8; ni++) {
            int col = n0 + nw + 8 * ni + 2 * lr;
            float* p0 = &Cp[(size_t)row0 * N + col];
            float* p1 = &Cp[(size_t)(row0 + 8) * N + col];
            p0[0] = acc[mi][ni][0] + bi0;
            p0[1] = acc[mi][ni][1] + bi0;
            p1[0] = acc[mi][ni][2] + bi1;
            p1[1] = acc[mi][ni][3] + bi1;
        }
    }
}

// ---------------------------------------------------------------------------
// fp16 tensor-core flash attention. Block = (bh, 128-row t-tile), 8 warps.
// Warp tile 16t x 64s; softmax in-warp.
//   qs2[cpair=32][t] stride 136 (uint4 fill; reads (8lr+lq) bijective)
//   ks2[cpair=32][s] stride 72  (uint4 fill; reads conflict-free)
//   vs2[c=64][spair] stride 36  (float4 gmem fill; reads conflict-free)
//   Ps2[t=128][spair] stride 36 (reg writes + reads conflict-free)
// scale^2 = 0.125 folded into q. fp32 accumulate + fp32 softmax.
// ---------------------------------------------------------------------------
__global__ __launch_bounds__(256, 2)
void attn_f16_kernel(const float* __restrict__ qkv,
                     float* __restrict__ aout) {
    extern __shared__ uint32_t smu[];
    uint32_t(*qs2)[136] = (uint32_t(*)[136])smu;           // [32][136] 17408 B
    uint32_t(*ks2)[72]  = (uint32_t(*)[72])(smu + 4352);   // [32][72]   9216 B
    uint32_t(*vs2)[36]  = (uint32_t(*)[36])(smu + 6656);   // [64][36]   9216 B
    uint32_t(*Ps2)[36]  = (uint32_t(*)[36])(smu + 8960);   // [128][36] 18432 B

    int bh = blockIdx.y;
    int t0 = blockIdx.x * 128;
    int b = bh >> 3, h = bh & 7;
    const float* base = qkv + ((size_t)b * 1536 + h * 192) * 1024;
    int tid = threadIdx.x;
    int lane = tid & 31;
    int warp = tid >> 5;
    int lq = lane >> 2;
    int lr = lane & 3;
    int rw = warp * 16;
    int r0 = rw + lq, r1 = rw + lq + 8;

    // Q -> qs2[cpair][t]: float4 pairs from rows 2cp, 2cp+1; fold 0.125
#pragma unroll
    for (int it = 0; it < 4; it++) {
        int i = tid + it * 256;            // 1024 tasks = 32cp x 32 t4
        int cp = i >> 5, t4 = (i & 31) * 4;
        const float* qp = base + (size_t)(2 * cp) * 1024 + t0 + t4;
        float4 lo = *(const float4*)qp;
        float4 hi = *(const float4*)(qp + 1024);
        uint4 st;
        st.x = pack_h2(lo.x * 0.125f, hi.x * 0.125f);
        st.y = pack_h2(lo.y * 0.125f, hi.y * 0.125f);
        st.z = pack_h2(lo.z * 0.125f, hi.z * 0.125f);
        st.w = pack_h2(lo.w * 0.125f, hi.w * 0.125f);
        *(uint4*)&qs2[cp][t4] = st;
    }

    float m0v = -INFINITY, m1v = -INFINITY, l0 = 0.f, l1 = 0.f;
    float accO[8][4] = {};
    __syncthreads();

    for (int s0 = 0; s0 < 1024; s0 += 64) {
        // K -> ks2[cpair][s]: float4 pairs from rows 64+2cp, 64+2cp+1
#pragma unroll
        for (int it = 0; it < 2; it++) {
            int i = tid + it * 256;        // 512 tasks = 32cp x 16 s4
            int cp = i >> 4, s4 = (i & 15) * 4;
            const float* kp_ = base + (size_t)(64 + 2 * cp) * 1024 + s0 + s4;
            float4 lo = *(const float4*)kp_;
            float4 hi = *(const float4*)(kp_ + 1024);
            uint4 st;
            st.x = pack_h2(lo.x, hi.x);
            st.y = pack_h2(lo.y, hi.y);
            st.z = pack_h2(lo.z, hi.z);
            st.w = pack_h2(lo.w, hi.w);
            *(uint4*)&ks2[cp][s4] = st;
        }
        // V -> vs2[c][spair] (float4 along s, 2 uint stores)
#pragma unroll
        for (int it = 0; it < 4; it++) {
            int i = tid + it * 256;
            int c = i >> 4, s4 = i & 15;
            float4 v = *(const float4*)&base[(size_t)(128 + c) * 1024 + s0 + s4 * 4];
            vs2[c][2 * s4]     = pack_h2(v.x, v.y);
            vs2[c][2 * s4 + 1] = pack_h2(v.z, v.w);
        }
        __syncthreads();

        // S = Q K^T : contraction over c (64 = 4 k16 steps)
        float accS[8][4] = {};
#pragma unroll
        for (int ks = 0; ks < 4; ks++) {
            int kb = ks * 8;
            uint32_t a[4];
            a[0] = qs2[kb + lr][r0];
            a[1] = qs2[kb + lr][r1];
            a[2] = qs2[kb + lr + 4][r0];
            a[3] = qs2[kb + lr + 4][r1];
#pragma unroll
            for (int ni = 0; ni < 8; ni++) {
                uint32_t bb[2];
                bb[0] = ks2[kb + lr][8 * ni + lq];
                bb[1] = ks2[kb + lr + 4][8 * ni + lq];
                mma_f16(accS[ni], a, bb);
            }
        }

        // Online softmax
        float rm0 = -INFINITY, rm1 = -INFINITY;
#pragma unroll
        for (int ni = 0; ni < 8; ni++) {
            rm0 = fmaxf(rm0, fmaxf(accS[ni][0], accS[ni][1]));
            rm1 = fmaxf(rm1, fmaxf(accS[ni][2], accS[ni][3]));
        }
        rm0 = fmaxf(rm0, __shfl_xor_sync(0xffffffffu, rm0, 1));
        rm0 = fmaxf(rm0, __shfl_xor_sync(0xffffffffu, rm0, 2));
        rm1 = fmaxf(rm1, __shfl_xor_sync(0xffffffffu, rm1, 1));
        rm1 = fmaxf(rm1, __shfl_xor_sync(0xffffffffu, rm1, 2));
        float mn0 = fmaxf(m0v, rm0), mn1 = fmaxf(m1v, rm1);
        float corr0 = __expf(m0v - mn0), corr1 = __expf(m1v - mn1);
        float ps0 = 0.f, ps1 = 0.f;
#pragma unroll
        for (int ni = 0; ni < 8; ni++) {
            float p00 = __expf(accS[ni][0] - mn0);
            float p01 = __expf(accS[ni][1] - mn0);
            float p10 = __expf(accS[ni][2] - mn1);
            float p11 = __expf(accS[ni][3] - mn1);
            ps0 += p00 + p01;
            ps1 += p10 + p11;
            Ps2[r0][4 * ni + lr] = pack_h2(p00, p01);
            Ps2[r1][4 * ni + lr] = pack_h2(p10, p11);
        }
        ps0 += __shfl_xor_sync(0xffffffffu, ps0, 1);
        ps0 += __shfl_xor_sync(0xffffffffu, ps0, 2);
        ps1 += __shfl_xor_sync(0xffffffffu, ps1, 1);
        ps1 += __shfl_xor_sync(0xffffffffu, ps1, 2);
        l0 = l0 * corr0 + ps0;
        l1 = l1 * corr1 + ps1;
        m0v = mn0; m1v = mn1;
#pragma unroll
        for (int ni = 0; ni < 8; ni++) {
            accO[ni][0] *= corr0; accO[ni][1] *= corr0;
            accO[ni][2] *= corr1; accO[ni][3] *= corr1;
        }
        __syncwarp();   // Ps2 rows read only by the writing warp

        // O += P V : contraction over s (64 = 4 k16 steps)
#pragma unroll
        for (int ks = 0; ks < 4; ks++) {
            int kb = ks * 8;
            uint32_t a[4];
            a[0] = Ps2[r0][kb + lr];
            a[1] = Ps2[r1][kb + lr];
            a[2] = Ps2[r0][kb + lr + 4];
            a[3] = Ps2[r1][kb + lr + 4];
#pragma unroll
            for (int ni = 0; ni < 8; ni++) {
                uint32_t bb[2];
                bb[0] = vs2[8 * ni + lq][kb + lr];
                bb[1] = vs2[8 * ni + lq][kb + lr + 4];
                mma_f16(accO[ni], a, bb);
            }
        }
        __syncthreads();   // tiles consumed before next-iter overwrite
    }

    // Epilogue: normalize, stage transposed [c][t], store.
    float inv0 = 1.0f / l0, inv1 = 1.0f / l1;
    float(*outS)[132] = (float(*)[132])smu;   // 64 x 132 floats = 33792 B
    __syncthreads();
#pragma unroll
    for (int ni = 0; ni < 8; ni++) {
        int c = 8 * ni + 2 * lr;
        outS[c][r0]     = accO[ni][0] * inv0;
        outS[c + 1][r0] = accO[ni][1] * inv0;
        outS[c][r1]     = accO[ni][2] * inv1;
        outS[c + 1][r1] = accO[ni][3] * inv1;
    }
    __syncthreads();

    size_t obase = ((size_t)b * 512 + h * 64) * 1024 + t0;
#pragma unroll
    for (int it = 0; it < 8; it++) {
        int i = tid + it * 256;
        int c = i >> 5, t4 = (i & 31) * 4;
        *(float4*)&aout[obase + (size_t)c * 1024 + t4] = *(const float4*)&outS[c][t4];
    }
}

// ---------------------------------------------------------------------------
// Launch
// ---------------------------------------------------------------------------
extern "C" void kernel_launch(void* const* d_in, const int* in_sizes, int n_in,
                              void* d_out, int out_size) {
    const float* x      = (const float*)d_in[0];
    const float* gn1_s  = (const float*)d_in[1];
    const float* gn1_b  = (const float*)d_in[2];
    const float* w_qkv  = (const float*)d_in[3];
    const float* b_qkv  = (const float*)d_in[4];
    const float* w_proj = (const float*)d_in[5];
    const float* b_proj = (const float*)d_in[6];
    const float* gn2_s  = (const float*)d_in[7];
    const float* gn2_b  = (const float*)d_in[8];
    float* out = (float*)d_out;

    float *hn, *qkv, *attn, *proj;
    cudaGetSymbolAddress((void**)&hn, g_hn);
    cudaGetSymbolAddress((void**)&qkv, g_qkv);
    cudaGetSymbolAddress((void**)&attn, g_attn);
    cudaGetSymbolAddress((void**)&proj, g_proj);

    const int ATTN_SMEM = (32 * 136 + 32 * 72 + 64 * 36 + 128 * 36) * 4;  // 54272 B
    cudaFuncSetAttribute(attn_f16_kernel, cudaFuncAttributeMaxDynamicSharedMemorySize,
                         ATTN_SMEM);

    // 1) GroupNorm1 (vectorized)
    gn_kernel<false><<<256, 1024>>>((const float4*)x, gn1_s, gn1_b, nullptr,
                                    (float4*)hn);
    // 2) qkv = W_qkv @ hn + b  (batched: 1536 x 1024 x 512, 8 batches)
    gemm_f16_kernel<<<dim3(8, 12, 8), 256>>>(w_qkv, hn, b_qkv, qkv, 1536, 1024, 512);
    // 3) fp16 tensor-core flash attention per (bh, 128-row t-tile)
    attn_f16_kernel<<<dim3(8, 64), 256, ATTN_SMEM>>>(qkv, attn);
    // 4) proj = W_proj @ a + b  (512 x 1024 x 512, 8 batches)
    gemm_f16_kernel<<<dim3(8, 4, 8), 256>>>(w_proj, attn, b_proj, proj, 512, 1024, 512);
    // 5) GroupNorm2 + residual (vectorized)
    gn_kernel<true><<<256, 1024>>>((const float4*)proj, gn2_s, gn2_b,
                                   (const float4*)x, (float4*)out);
}